// round 8
// baseline (speedup 1.0000x reference)
#include <cuda_runtime.h>

// NavierStokesPINN1 — ReLU MLP is piecewise linear; outputs reduce to
//   u = dpsi/dy, v = -dpsi/dx, p, f = dp/dx, g = dp/dy.
// Forward pass reproduces the reference's fp32 rounding exactly (single acc,
// k ascending, fma per step, bias after reduction) so every ReLU mask matches.
// R8: 12 warps/CTA (3/SMSP) via CHUNK=16 weight staging; forward neuron-pair
// packing (weights as native u64 pairs from smem, activations pre-duplicated
// (h,h) in per-warp tables); backward runs as two 4-point half-passes to
// halve accumulator registers (weights re-streamed, L2-resident).

#define H        256
#define NL       4
#define NPTS     65536
#define WP       8
#define THREADS  384
#define WARPS    12
#define PTS_PER_CTA (WARPS * WP)    // 96
#define CHUNK    16
#define CHUNK_FLOATS (CHUNK * H)    // 4096 floats = 16KB
#define NCHUNKS  192                // 64 fwd + 2*64 bwd

typedef unsigned long long u64;

__device__ float g_WhT[NL * H * H];   // transposed hidden weights (backward)

__device__ __forceinline__ u64 pack2(float lo, float hi) {
    u64 r; asm("mov.b64 %0, {%1, %2};" : "=l"(r) : "f"(lo), "f"(hi)); return r;
}
__device__ __forceinline__ void unpack2(u64 v, float& lo, float& hi) {
    asm("mov.b64 {%0, %1}, %2;" : "=f"(lo), "=f"(hi) : "l"(v));
}
__device__ __forceinline__ u64 ffma2(u64 a, u64 b, u64 c) {
    u64 d; asm("fma.rn.f32x2 %0, %1, %2, %3;" : "=l"(d) : "l"(a), "l"(b), "l"(c));
    return d;
}

__device__ __forceinline__ void cp_async16(void* s, const void* g) {
    unsigned sa = (unsigned)__cvta_generic_to_shared(s);
    asm volatile("cp.async.cg.shared.global [%0], [%1], 16;" :: "r"(sa), "l"(g));
}
__device__ __forceinline__ void cp_commit() { asm volatile("cp.async.commit_group;"); }
template<int NN> __device__ __forceinline__ void cp_wait() {
    asm volatile("cp.async.wait_group %0;" :: "n"(NN));
}

__device__ __forceinline__ void stage_chunk(float* dst, const float* src, int tid) {
    #pragma unroll
    for (int q = 0; q < 3; ++q) {                  // 1024 float4 / 384 threads
        int fi = q * THREADS + tid;
        if (fi < CHUNK_FLOATS / 4)
            cp_async16(((float4*)dst) + fi, ((const float4*)src) + fi);
    }
    cp_commit();
}

// chunks 0..63 = Wh layers 0..3 (forward);
// chunks 64..191 = g_WhT layers 3,2,1,0 twice (two backward half-passes).
__device__ __forceinline__ const float* chunk_src(int c, const float* Wh) {
    if (c < 64) return Wh + c * CHUNK_FLOATS;
    int cc = (c - 64) & 63;
    int l = 3 - (cc >> 4);
    return g_WhT + (l << 16) + (cc & 15) * CHUNK_FLOATS;
}

__global__ void prep_kernel(const float* __restrict__ Wh) {
    int i = blockIdx.x * blockDim.x + threadIdx.x;
    float v = __ldg(Wh + i);
    int l = i >> 16;
    int rem = i & 0xFFFF;
    int k = rem >> 8, j = rem & 0xFF;
    g_WhT[(l << 16) + (j << 8) + k] = v;
}

// lane owns neurons j = 128*(ln>>2) + 4*lane + (ln&3), ln = 0..7
#define JN(ln) ((((ln) >> 2) << 7) + (lane << 2) + ((ln) & 3))
// mask bit for (point pt 0..7, local neuron ln 0..7)
#define MB(pt, ln) ((u64)1 << (((pt) << 3) + (ln)))

__global__ void __launch_bounds__(THREADS, 1)
pinn_kernel(const float* __restrict__ x, const float* __restrict__ y,
            const float* __restrict__ t,
            const float* __restrict__ Win,  const float* __restrict__ b_in,
            const float* __restrict__ Wh,   const float* __restrict__ b_h,
            const float* __restrict__ Wout, const float* __restrict__ b_out,
            float* __restrict__ out)
{
    extern __shared__ float Ws[];   // [2][CHUNK][H] weights (32KB) + tables
    const int tid  = threadIdx.x;
    const int lane = tid & 31;
    const int warp = tid >> 5;
    const int base = blockIdx.x * PTS_PER_CTA + warp * WP;

    // per-warp 2048-u64 (16KB) table region
    u64* tabW = (u64*)(Ws + 2 * CHUNK_FLOATS) + (size_t)warp * 2048;
    u64* tabF = tabW;            // fwd: [pt*256 + j] = (h,h) duplicated
    u64* tb0  = tabW;            // bwd psi stream: [(q2<<8)+j] point-pair packed
    u64* tb1  = tabW + 512;      // bwd p stream

    stage_chunk(Ws, chunk_src(0, Wh), tid);

    // ---------------- input layer (exact GEMM rounding order) ----------------
    u64 Mi = 0, Mh[NL];
    {
        float rx[WP], ry[WP], rt[WP];
        #pragma unroll
        for (int p = 0; p < WP; ++p) {
            int idx = min(base + p, NPTS - 1);
            rx[p] = x[idx]; ry[p] = y[idx]; rt[p] = t[idx];
        }
        #pragma unroll
        for (int ln = 0; ln < 8; ++ln) {
            int j = JN(ln);
            float w0 = __ldg(Win + j);
            float w1 = __ldg(Win + H + j);
            float w2 = __ldg(Win + 2 * H + j);
            float bb = __ldg(b_in + j);
            #pragma unroll
            for (int p = 0; p < WP; ++p) {
                float acc = fmaf(rx[p], w0, 0.f);
                acc = fmaf(ry[p], w1, acc);
                acc = fmaf(rt[p], w2, acc);
                float a = acc + bb;
                bool m = a > 0.f;
                Mi |= m ? MB(p, ln) : 0ull;
                float hv = m ? a : 0.f;
                tabF[(p << 8) + j] = pack2(hv, hv);
            }
        }
    }
    __syncwarp();

    // ---------------- forward hidden layers (neuron-pair packing) ----------------
    float pp[WP];
    #pragma unroll
    for (int p = 0; p < WP; ++p) pp[p] = 0.f;
    int c = 0;

    #pragma unroll 1
    for (int l = 0; l < NL; ++l) {
        u64 acc[WP][4];             // [point][neuron-pair]
        #pragma unroll
        for (int p = 0; p < WP; ++p)
            #pragma unroll
            for (int np = 0; np < 4; ++np) acc[p][np] = 0ull;

        #pragma unroll 1
        for (int r = 0; r < 16; ++r, ++c) {
            stage_chunk(Ws + ((c + 1) & 1) * CHUNK_FLOATS, chunk_src(c + 1, Wh), tid);
            cp_wait<1>();
            __syncthreads();

            const float* wb = Ws + (c & 1) * CHUNK_FLOATS + (lane << 2);
            const u64* tf = tabF + (r << 4);
            #pragma unroll 4
            for (int kl = 0; kl < CHUNK; ++kl) {
                ulonglong2 WA = *(const ulonglong2*)(wb + kl * H);        // (w0,w1),(w2,w3)
                ulonglong2 WB = *(const ulonglong2*)(wb + kl * H + 128);  // (w4,w5),(w6,w7)
                #pragma unroll
                for (int p = 0; p < WP; ++p) {
                    u64 b = tf[(p << 8) + kl];
                    acc[p][0] = ffma2(b, WA.x, acc[p][0]);
                    acc[p][1] = ffma2(b, WA.y, acc[p][1]);
                    acc[p][2] = ffma2(b, WB.x, acc[p][2]);
                    acc[p][3] = ffma2(b, WB.y, acc[p][3]);
                }
            }
            __syncthreads();
        }

        // epilogue: bias AFTER reduction, relu, record mask
        u64 Ml = 0;
        #pragma unroll
        for (int np = 0; np < 4; ++np) {
            int ln0 = 2 * np;
            int j0 = JN(ln0);                 // j1 = j0 + 1
            float bb0 = __ldg(b_h + l * H + j0);
            float bb1 = __ldg(b_h + l * H + j0 + 1);
            if (l < NL - 1) {
                #pragma unroll
                for (int p = 0; p < WP; ++p) {
                    float a0, a1; unpack2(acc[p][np], a0, a1);
                    float v0 = a0 + bb0, v1 = a1 + bb1;
                    bool m0 = v0 > 0.f, m1 = v1 > 0.f;
                    Ml |= (m0 ? MB(p, ln0) : 0ull) | (m1 ? MB(p, ln0 + 1) : 0ull);
                    tabF[(p << 8) + j0]     = pack2(m0 ? v0 : 0.f, m0 ? v0 : 0.f);
                    tabF[(p << 8) + j0 + 1] = pack2(m1 ? v1 : 0.f, m1 ? v1 : 0.f);
                }
            } else {
                float wo10 = __ldg(Wout + 2 * j0 + 1);
                float wo11 = __ldg(Wout + 2 * (j0 + 1) + 1);
                #pragma unroll
                for (int p = 0; p < WP; ++p) {
                    float a0, a1; unpack2(acc[p][np], a0, a1);
                    float v0 = a0 + bb0, v1 = a1 + bb1;
                    bool m0 = v0 > 0.f, m1 = v1 > 0.f;
                    Ml |= (m0 ? MB(p, ln0) : 0ull) | (m1 ? MB(p, ln0 + 1) : 0ull);
                    pp[p] = fmaf(m0 ? v0 : 0.f, wo10, pp[p]);
                    pp[p] = fmaf(m1 ? v1 : 0.f, wo11, pp[p]);
                }
            }
        }
        Mh[l] = Ml;
        __syncwarp();
    }

    // p output: warp-reduce and store
    #pragma unroll
    for (int off = 16; off > 0; off >>= 1)
        #pragma unroll
        for (int p = 0; p < WP; ++p)
            pp[p] += __shfl_xor_sync(0xffffffffu, pp[p], off);
    if (lane == 0) {
        float bo1 = __ldg(b_out + 1);
        #pragma unroll
        for (int p = 0; p < WP; ++p)
            if (base + p < NPTS) out[2 * NPTS + base + p] = pp[p] + bo1;
    }

    // ---------------- backward: two 4-point half-passes ----------------
    #pragma unroll 1
    for (int half = 0; half < 2; ++half) {
        const int P0 = half * 4;    // points P0..P0+3, pairs q2=0,1

        // init: masked layer-3 cotangents into tables (point-pair packed)
        #pragma unroll
        for (int ln = 0; ln < 8; ++ln) {
            int j = JN(ln);
            float a0 = __ldg(Wout + 2 * j);       // psi
            float a1 = __ldg(Wout + 2 * j + 1);   // p
            #pragma unroll
            for (int q2 = 0; q2 < 2; ++q2) {
                bool mlo = (Mh[3] & MB(P0 + 2 * q2, ln)) != 0ull;
                bool mhi = (Mh[3] & MB(P0 + 2 * q2 + 1, ln)) != 0ull;
                tb0[(q2 << 8) + j] = pack2(mlo ? a0 : 0.f, mhi ? a0 : 0.f);
                tb1[(q2 << 8) + j] = pack2(mlo ? a1 : 0.f, mhi ? a1 : 0.f);
            }
        }
        __syncwarp();

        u64 na0[2][8], na1[2][8];

        #pragma unroll 1
        for (int bl = 3; bl >= 0; --bl) {
            #pragma unroll
            for (int q2 = 0; q2 < 2; ++q2)
                #pragma unroll
                for (int i = 0; i < 8; ++i) { na0[q2][i] = 0ull; na1[q2][i] = 0ull; }

            #pragma unroll 1
            for (int r = 0; r < 16; ++r, ++c) {
                if (c + 1 < NCHUNKS) {
                    stage_chunk(Ws + ((c + 1) & 1) * CHUNK_FLOATS, chunk_src(c + 1, Wh), tid);
                    cp_wait<1>();
                } else {
                    cp_wait<0>();
                }
                __syncthreads();

                const float* wb = Ws + (c & 1) * CHUNK_FLOATS + (lane << 2);
                const u64* t0 = tb0 + (r << 4);
                const u64* t1 = tb1 + (r << 4);
                #pragma unroll 4
                for (int kl = 0; kl < CHUNK; ++kl) {
                    float4 wA = *(const float4*)(wb + kl * H);
                    float4 wB = *(const float4*)(wb + kl * H + 128);
                    u64 w0 = pack2(wA.x, wA.x), w1 = pack2(wA.y, wA.y);
                    u64 w2 = pack2(wA.z, wA.z), w3 = pack2(wA.w, wA.w);
                    u64 w4 = pack2(wB.x, wB.x), w5 = pack2(wB.y, wB.y);
                    u64 w6 = pack2(wB.z, wB.z), w7 = pack2(wB.w, wB.w);
                    #pragma unroll
                    for (int q2 = 0; q2 < 2; ++q2) {
                        u64 b0 = t0[(q2 << 8) + kl];
                        u64 b1 = t1[(q2 << 8) + kl];
                        na0[q2][0] = ffma2(b0, w0, na0[q2][0]);
                        na0[q2][1] = ffma2(b0, w1, na0[q2][1]);
                        na0[q2][2] = ffma2(b0, w2, na0[q2][2]);
                        na0[q2][3] = ffma2(b0, w3, na0[q2][3]);
                        na0[q2][4] = ffma2(b0, w4, na0[q2][4]);
                        na0[q2][5] = ffma2(b0, w5, na0[q2][5]);
                        na0[q2][6] = ffma2(b0, w6, na0[q2][6]);
                        na0[q2][7] = ffma2(b0, w7, na0[q2][7]);
                        na1[q2][0] = ffma2(b1, w0, na1[q2][0]);
                        na1[q2][1] = ffma2(b1, w1, na1[q2][1]);
                        na1[q2][2] = ffma2(b1, w2, na1[q2][2]);
                        na1[q2][3] = ffma2(b1, w3, na1[q2][3]);
                        na1[q2][4] = ffma2(b1, w4, na1[q2][4]);
                        na1[q2][5] = ffma2(b1, w5, na1[q2][5]);
                        na1[q2][6] = ffma2(b1, w6, na1[q2][6]);
                        na1[q2][7] = ffma2(b1, w7, na1[q2][7]);
                    }
                }
                __syncthreads();
            }

            if (bl > 0) {   // mask by previous layer, refill tables
                u64 Mp = Mh[bl - 1];
                #pragma unroll
                for (int ln = 0; ln < 8; ++ln) {
                    int j = JN(ln);
                    #pragma unroll
                    for (int q2 = 0; q2 < 2; ++q2) {
                        bool mlo = (Mp & MB(P0 + 2 * q2, ln)) != 0ull;
                        bool mhi = (Mp & MB(P0 + 2 * q2 + 1, ln)) != 0ull;
                        float l0, h0, l1, h1;
                        unpack2(na0[q2][ln], l0, h0);
                        unpack2(na1[q2][ln], l1, h1);
                        tb0[(q2 << 8) + j] = pack2(mlo ? l0 : 0.f, mhi ? h0 : 0.f);
                        tb1[(q2 << 8) + j] = pack2(mlo ? l1 : 0.f, mhi ? h1 : 0.f);
                    }
                }
                __syncwarp();
            }
        }

        // input-layer backward for this half's 4 points
        float su[4], sv[4], sf[4], sg[4];
        #pragma unroll
        for (int q = 0; q < 4; ++q) { su[q] = sv[q] = sf[q] = sg[q] = 0.f; }

        #pragma unroll
        for (int ln = 0; ln < 8; ++ln) {
            int j = JN(ln);
            float wx = __ldg(Win + j);
            float wy = __ldg(Win + H + j);
            #pragma unroll
            for (int q2 = 0; q2 < 2; ++q2) {
                float g0[2], g1[2];
                unpack2(na0[q2][ln], g0[0], g0[1]);
                unpack2(na1[q2][ln], g1[0], g1[1]);
                #pragma unroll
                for (int hh = 0; hh < 2; ++hh) {
                    int q = 2 * q2 + hh;
                    bool m = (Mi & MB(P0 + q, ln)) != 0ull;
                    float r0 = m ? g0[hh] : 0.f;
                    float r1 = m ? g1[hh] : 0.f;
                    su[q] = fmaf(wy, r0, su[q]);
                    sv[q] = fmaf(wx, r0, sv[q]);
                    sf[q] = fmaf(wx, r1, sf[q]);
                    sg[q] = fmaf(wy, r1, sg[q]);
                }
            }
        }

        #pragma unroll
        for (int off = 16; off > 0; off >>= 1) {
            #pragma unroll
            for (int q = 0; q < 4; ++q) {
                su[q] += __shfl_xor_sync(0xffffffffu, su[q], off);
                sv[q] += __shfl_xor_sync(0xffffffffu, sv[q], off);
                sf[q] += __shfl_xor_sync(0xffffffffu, sf[q], off);
                sg[q] += __shfl_xor_sync(0xffffffffu, sg[q], off);
            }
        }
        if (lane == 0) {
            #pragma unroll
            for (int q = 0; q < 4; ++q) {
                int pt = base + P0 + q;
                if (pt < NPTS) {
                    out[0 * NPTS + pt] =  su[q];
                    out[1 * NPTS + pt] = -sv[q];
                    out[3 * NPTS + pt] =  sf[q];
                    out[4 * NPTS + pt] =  sg[q];
                }
            }
        }
    }
}

extern "C" void kernel_launch(void* const* d_in, const int* in_sizes, int n_in,
                              void* d_out, int out_size)
{
    const float* x     = (const float*)d_in[0];
    const float* y     = (const float*)d_in[1];
    const float* t     = (const float*)d_in[2];
    const float* Win   = (const float*)d_in[3];
    const float* b_in  = (const float*)d_in[4];
    const float* Wh    = (const float*)d_in[5];
    const float* b_h   = (const float*)d_in[6];
    const float* Wout  = (const float*)d_in[7];
    const float* b_out = (const float*)d_in[8];
    float* out = (float*)d_out;

    prep_kernel<<<(NL * H * H) / 256, 256>>>(Wh);

    // 32KB weight double-buffer + 12 warps * 16KB tables = 224KB
    const int smem = 2 * CHUNK_FLOATS * (int)sizeof(float)
                   + WARPS * 2048 * (int)sizeof(u64);
    cudaFuncSetAttribute(pinn_kernel, cudaFuncAttributeMaxDynamicSharedMemorySize, smem);
    const int grid = (NPTS + PTS_PER_CTA - 1) / PTS_PER_CTA;   // 683
    pinn_kernel<<<grid, THREADS, smem>>>(x, y, t, Win, b_in, Wh, b_h,
                                         Wout, b_out, out);
}

// round 9
// speedup vs baseline: 1.2322x; 1.2322x over previous
#include <cuda_runtime.h>

// NavierStokesPINN1 — ReLU MLP is piecewise linear; outputs reduce to
//   u = dpsi/dy, v = -dpsi/dx, p, f = dp/dx, g = dp/dy.
// Forward pass reproduces the reference's fp32 rounding exactly (single acc,
// k ascending, fma per step, bias after reduction) so every ReLU mask matches.
// R9 = R7 structure (8 warps, WP8, CHUNK32, 64 chunks, full-width backward)
// + R8's forward neuron-pair packing: weights consumed as native u64 pairs
// from smem (no duplication movs), activations pre-duplicated (h,h) in
// per-warp smem tables. Backward: 2 cotangent streams, point-pair packed,
// via transposed weights.

#define H        256
#define NL       4
#define NPTS     65536
#define WP       8                  // points per warp
#define THREADS  256
#define WARPS    8
#define PTS_PER_CTA (WARPS * WP)    // 64
#define CHUNK    32
#define CHUNK_FLOATS (CHUNK * H)    // 8192 floats = 32KB

typedef unsigned long long u64;

__device__ float g_WhT[NL * H * H];   // transposed hidden weights (backward)

__device__ __forceinline__ u64 pack2(float lo, float hi) {
    u64 r; asm("mov.b64 %0, {%1, %2};" : "=l"(r) : "f"(lo), "f"(hi)); return r;
}
__device__ __forceinline__ void unpack2(u64 v, float& lo, float& hi) {
    asm("mov.b64 {%0, %1}, %2;" : "=f"(lo), "=f"(hi) : "l"(v));
}
__device__ __forceinline__ u64 ffma2(u64 a, u64 b, u64 c) {
    u64 d; asm("fma.rn.f32x2 %0, %1, %2, %3;" : "=l"(d) : "l"(a), "l"(b), "l"(c));
    return d;
}

__device__ __forceinline__ void cp_async16(void* s, const void* g) {
    unsigned sa = (unsigned)__cvta_generic_to_shared(s);
    asm volatile("cp.async.cg.shared.global [%0], [%1], 16;" :: "r"(sa), "l"(g));
}
__device__ __forceinline__ void cp_commit() { asm volatile("cp.async.commit_group;"); }
template<int NN> __device__ __forceinline__ void cp_wait() {
    asm volatile("cp.async.wait_group %0;" :: "n"(NN));
}

__device__ __forceinline__ void stage_chunk(float* dst, const float* src, int tid) {
    #pragma unroll
    for (int q = 0; q < CHUNK_FLOATS / 4 / THREADS; ++q) {   // 8 float4/thread
        int fi = q * THREADS + tid;
        cp_async16(((float4*)dst) + fi, ((const float4*)src) + fi);
    }
    cp_commit();
}

// chunks 0..31 = Wh layers 0..3 (forward), 32..63 = g_WhT layers 3,2,1,0.
__device__ __forceinline__ const float* chunk_src(int c, const float* Wh) {
    if (c < 32) return Wh + c * CHUNK_FLOATS;
    int cc = c - 32;
    int l = 3 - (cc >> 3);
    return g_WhT + (l << 16) + (cc & 7) * CHUNK_FLOATS;
}

__global__ void prep_kernel(const float* __restrict__ Wh) {
    int i = blockIdx.x * blockDim.x + threadIdx.x;
    float v = __ldg(Wh + i);
    int l = i >> 16;
    int rem = i & 0xFFFF;
    int k = rem >> 8, j = rem & 0xFF;
    g_WhT[(l << 16) + (j << 8) + k] = v;
}

// lane owns neurons j = 128*(ln>>2) + 4*lane + (ln&3), ln = 0..7
#define JN(ln) ((((ln) >> 2) << 7) + (lane << 2) + ((ln) & 3))
// mask bit for (point pt 0..7, local neuron ln 0..7)
#define MB(pt, ln) ((u64)1 << (((pt) << 3) + (ln)))

__global__ void __launch_bounds__(THREADS, 1)
pinn_kernel(const float* __restrict__ x, const float* __restrict__ y,
            const float* __restrict__ t,
            const float* __restrict__ Win,  const float* __restrict__ b_in,
            const float* __restrict__ Wh,   const float* __restrict__ b_h,
            const float* __restrict__ Wout, const float* __restrict__ b_out,
            float* __restrict__ out)
{
    extern __shared__ float Ws[];   // [2][CHUNK][H] weights (64KB) + tables
    const int tid  = threadIdx.x;
    const int lane = tid & 31;
    const int warp = tid >> 5;
    const int base = blockIdx.x * PTS_PER_CTA + warp * WP;

    // per-warp 2048-u64 (16KB) table region
    u64* tabW = (u64*)(Ws + 2 * CHUNK_FLOATS) + (size_t)warp * 2048;
    u64* tabF = tabW;            // fwd: [pt*256 + j] = (h,h) duplicated
    u64* tb0  = tabW;            // bwd psi stream: [(q<<8)+j] point-pair packed
    u64* tb1  = tabW + 1024;     // bwd p stream

    stage_chunk(Ws, chunk_src(0, Wh), tid);

    // ---------------- input layer (exact GEMM rounding order) ----------------
    u64 Mi = 0, Mh[NL];
    {
        float rx[WP], ry[WP], rt[WP];
        #pragma unroll
        for (int p = 0; p < WP; ++p) {
            rx[p] = x[base + p]; ry[p] = y[base + p]; rt[p] = t[base + p];
        }
        #pragma unroll
        for (int ln = 0; ln < 8; ++ln) {
            int j = JN(ln);
            float w0 = __ldg(Win + j);
            float w1 = __ldg(Win + H + j);
            float w2 = __ldg(Win + 2 * H + j);
            float bb = __ldg(b_in + j);
            #pragma unroll
            for (int p = 0; p < WP; ++p) {
                float acc = fmaf(rx[p], w0, 0.f);
                acc = fmaf(ry[p], w1, acc);
                acc = fmaf(rt[p], w2, acc);
                float a = acc + bb;
                bool m = a > 0.f;
                Mi |= m ? MB(p, ln) : 0ull;
                float hv = m ? a : 0.f;
                tabF[(p << 8) + j] = pack2(hv, hv);
            }
        }
    }
    __syncwarp();

    // ---------------- forward hidden layers (neuron-pair packing) ----------------
    float pp[WP];
    #pragma unroll
    for (int p = 0; p < WP; ++p) pp[p] = 0.f;
    int c = 0;

    #pragma unroll 1
    for (int l = 0; l < NL; ++l) {
        u64 acc[WP][4];             // [point][neuron-pair (2np, 2np+1)]
        #pragma unroll
        for (int p = 0; p < WP; ++p)
            #pragma unroll
            for (int np = 0; np < 4; ++np) acc[p][np] = 0ull;

        #pragma unroll 2
        for (int r = 0; r < 8; ++r, ++c) {
            stage_chunk(Ws + ((c + 1) & 1) * CHUNK_FLOATS, chunk_src(c + 1, Wh), tid);
            cp_wait<1>();
            __syncthreads();

            const float* wb = Ws + (c & 1) * CHUNK_FLOATS + (lane << 2);
            const u64* tf = tabF + (r << 5);
            #pragma unroll 4
            for (int kl = 0; kl < CHUNK; ++kl) {
                ulonglong2 WA = *(const ulonglong2*)(wb + kl * H);        // (w0,w1),(w2,w3)
                ulonglong2 WB = *(const ulonglong2*)(wb + kl * H + 128);  // (w4,w5),(w6,w7)
                #pragma unroll
                for (int p = 0; p < WP; ++p) {
                    u64 b = tf[(p << 8) + kl];
                    acc[p][0] = ffma2(b, WA.x, acc[p][0]);
                    acc[p][1] = ffma2(b, WA.y, acc[p][1]);
                    acc[p][2] = ffma2(b, WB.x, acc[p][2]);
                    acc[p][3] = ffma2(b, WB.y, acc[p][3]);
                }
            }
            __syncthreads();
        }

        // epilogue: bias AFTER reduction, relu, record mask
        u64 Ml = 0;
        #pragma unroll
        for (int np = 0; np < 4; ++np) {
            int ln0 = 2 * np;
            int j0 = JN(ln0);                 // j1 = j0 + 1
            float bb0 = __ldg(b_h + l * H + j0);
            float bb1 = __ldg(b_h + l * H + j0 + 1);
            if (l < NL - 1) {
                #pragma unroll
                for (int p = 0; p < WP; ++p) {
                    float a0, a1; unpack2(acc[p][np], a0, a1);
                    float v0 = a0 + bb0, v1 = a1 + bb1;
                    bool m0 = v0 > 0.f, m1 = v1 > 0.f;
                    Ml |= (m0 ? MB(p, ln0) : 0ull) | (m1 ? MB(p, ln0 + 1) : 0ull);
                    tabF[(p << 8) + j0]     = pack2(m0 ? v0 : 0.f, m0 ? v0 : 0.f);
                    tabF[(p << 8) + j0 + 1] = pack2(m1 ? v1 : 0.f, m1 ? v1 : 0.f);
                }
            } else {
                float wo10 = __ldg(Wout + 2 * j0 + 1);
                float wo11 = __ldg(Wout + 2 * (j0 + 1) + 1);
                #pragma unroll
                for (int p = 0; p < WP; ++p) {
                    float a0, a1; unpack2(acc[p][np], a0, a1);
                    float v0 = a0 + bb0, v1 = a1 + bb1;
                    bool m0 = v0 > 0.f, m1 = v1 > 0.f;
                    Ml |= (m0 ? MB(p, ln0) : 0ull) | (m1 ? MB(p, ln0 + 1) : 0ull);
                    pp[p] = fmaf(m0 ? v0 : 0.f, wo10, pp[p]);
                    pp[p] = fmaf(m1 ? v1 : 0.f, wo11, pp[p]);
                }
            }
        }
        Mh[l] = Ml;
        __syncwarp();
    }

    // p output: warp-reduce and store
    #pragma unroll
    for (int off = 16; off > 0; off >>= 1)
        #pragma unroll
        for (int p = 0; p < WP; ++p)
            pp[p] += __shfl_xor_sync(0xffffffffu, pp[p], off);
    if (lane == 0) {
        float bo1 = __ldg(b_out + 1);
        #pragma unroll
        for (int p = 0; p < WP; ++p)
            out[2 * NPTS + base + p] = pp[p] + bo1;
    }

    // ---------------- backward init: masked layer-3 cotangents ----------------
    // (tabF no longer needed; tb0/tb1 reuse its region)
    #pragma unroll
    for (int ln = 0; ln < 8; ++ln) {
        int j = JN(ln);
        float a0 = __ldg(Wout + 2 * j);       // psi stream
        float a1 = __ldg(Wout + 2 * j + 1);   // p stream
        #pragma unroll
        for (int q = 0; q < 4; ++q) {
            bool mlo = (Mh[3] & MB(2 * q, ln)) != 0ull;
            bool mhi = (Mh[3] & MB(2 * q + 1, ln)) != 0ull;
            tb0[(q << 8) + j] = pack2(mlo ? a0 : 0.f, mhi ? a0 : 0.f);
            tb1[(q << 8) + j] = pack2(mlo ? a1 : 0.f, mhi ? a1 : 0.f);
        }
    }
    __syncwarp();

    // ---------------- backward hidden layers (point-pair packing) ----------------
    u64 na0[4][8], na1[4][8];

    #pragma unroll 1
    for (int bl = 3; bl >= 0; --bl) {
        #pragma unroll
        for (int q = 0; q < 4; ++q)
            #pragma unroll
            for (int i = 0; i < 8; ++i) { na0[q][i] = 0ull; na1[q][i] = 0ull; }

        #pragma unroll 2
        for (int r = 0; r < 8; ++r, ++c) {
            if (c < 63) {
                stage_chunk(Ws + ((c + 1) & 1) * CHUNK_FLOATS, chunk_src(c + 1, Wh), tid);
                cp_wait<1>();
            } else {
                cp_wait<0>();
            }
            __syncthreads();

            const float* wb = Ws + (c & 1) * CHUNK_FLOATS + (lane << 2);
            const u64* t0 = tb0 + (r << 5);
            const u64* t1 = tb1 + (r << 5);
            #pragma unroll 4
            for (int kl = 0; kl < CHUNK; ++kl) {
                float4 wA = *(const float4*)(wb + kl * H);
                float4 wB = *(const float4*)(wb + kl * H + 128);
                u64 w0 = pack2(wA.x, wA.x), w1 = pack2(wA.y, wA.y);
                u64 w2 = pack2(wA.z, wA.z), w3 = pack2(wA.w, wA.w);
                u64 w4 = pack2(wB.x, wB.x), w5 = pack2(wB.y, wB.y);
                u64 w6 = pack2(wB.z, wB.z), w7 = pack2(wB.w, wB.w);
                #pragma unroll
                for (int q = 0; q < 4; ++q) {
                    u64 b0 = t0[(q << 8) + kl];
                    u64 b1 = t1[(q << 8) + kl];
                    na0[q][0] = ffma2(b0, w0, na0[q][0]);
                    na0[q][1] = ffma2(b0, w1, na0[q][1]);
                    na0[q][2] = ffma2(b0, w2, na0[q][2]);
                    na0[q][3] = ffma2(b0, w3, na0[q][3]);
                    na0[q][4] = ffma2(b0, w4, na0[q][4]);
                    na0[q][5] = ffma2(b0, w5, na0[q][5]);
                    na0[q][6] = ffma2(b0, w6, na0[q][6]);
                    na0[q][7] = ffma2(b0, w7, na0[q][7]);
                    na1[q][0] = ffma2(b1, w0, na1[q][0]);
                    na1[q][1] = ffma2(b1, w1, na1[q][1]);
                    na1[q][2] = ffma2(b1, w2, na1[q][2]);
                    na1[q][3] = ffma2(b1, w3, na1[q][3]);
                    na1[q][4] = ffma2(b1, w4, na1[q][4]);
                    na1[q][5] = ffma2(b1, w5, na1[q][5]);
                    na1[q][6] = ffma2(b1, w6, na1[q][6]);
                    na1[q][7] = ffma2(b1, w7, na1[q][7]);
                }
            }
            __syncthreads();
        }

        if (bl > 0) {   // mask by previous layer, refill tables
            u64 Mp = Mh[bl - 1];
            #pragma unroll
            for (int ln = 0; ln < 8; ++ln) {
                int j = JN(ln);
                #pragma unroll
                for (int q = 0; q < 4; ++q) {
                    bool mlo = (Mp & MB(2 * q, ln)) != 0ull;
                    bool mhi = (Mp & MB(2 * q + 1, ln)) != 0ull;
                    float l0, h0, l1, h1;
                    unpack2(na0[q][ln], l0, h0);
                    unpack2(na1[q][ln], l1, h1);
                    tb0[(q << 8) + j] = pack2(mlo ? l0 : 0.f, mhi ? h0 : 0.f);
                    tb1[(q << 8) + j] = pack2(mlo ? l1 : 0.f, mhi ? h1 : 0.f);
                }
            }
            __syncwarp();
        }
    }

    // ---------------- input-layer backward + outputs ----------------
    float su[WP], sv[WP], sf[WP], sg[WP];
    #pragma unroll
    for (int p = 0; p < WP; ++p) { su[p] = sv[p] = sf[p] = sg[p] = 0.f; }

    #pragma unroll
    for (int ln = 0; ln < 8; ++ln) {
        int j = JN(ln);
        float wx = __ldg(Win + j);
        float wy = __ldg(Win + H + j);
        #pragma unroll
        for (int q = 0; q < 4; ++q) {
            float g0[2], g1[2];
            unpack2(na0[q][ln], g0[0], g0[1]);
            unpack2(na1[q][ln], g1[0], g1[1]);
            #pragma unroll
            for (int hh = 0; hh < 2; ++hh) {
                int p = 2 * q + hh;
                bool m = (Mi & MB(p, ln)) != 0ull;
                float r0 = m ? g0[hh] : 0.f;
                float r1 = m ? g1[hh] : 0.f;
                su[p] = fmaf(wy, r0, su[p]);
                sv[p] = fmaf(wx, r0, sv[p]);
                sf[p] = fmaf(wx, r1, sf[p]);
                sg[p] = fmaf(wy, r1, sg[p]);
            }
        }
    }

    #pragma unroll
    for (int off = 16; off > 0; off >>= 1) {
        #pragma unroll
        for (int p = 0; p < WP; ++p) {
            su[p] += __shfl_xor_sync(0xffffffffu, su[p], off);
            sv[p] += __shfl_xor_sync(0xffffffffu, sv[p], off);
            sf[p] += __shfl_xor_sync(0xffffffffu, sf[p], off);
            sg[p] += __shfl_xor_sync(0xffffffffu, sg[p], off);
        }
    }
    if (lane == 0) {
        #pragma unroll
        for (int p = 0; p < WP; ++p) {
            int pt = base + p;
            out[0 * NPTS + pt] =  su[p];
            out[1 * NPTS + pt] = -sv[p];
            out[3 * NPTS + pt] =  sf[p];
            out[4 * NPTS + pt] =  sg[p];
        }
    }
}

extern "C" void kernel_launch(void* const* d_in, const int* in_sizes, int n_in,
                              void* d_out, int out_size)
{
    const float* x     = (const float*)d_in[0];
    const float* y     = (const float*)d_in[1];
    const float* t     = (const float*)d_in[2];
    const float* Win   = (const float*)d_in[3];
    const float* b_in  = (const float*)d_in[4];
    const float* Wh    = (const float*)d_in[5];
    const float* b_h   = (const float*)d_in[6];
    const float* Wout  = (const float*)d_in[7];
    const float* b_out = (const float*)d_in[8];
    float* out = (float*)d_out;

    prep_kernel<<<(NL * H * H) / 256, 256>>>(Wh);

    // 64KB weight double-buffer + 8 warps * 16KB tables = 192KB
    const int smem = 2 * CHUNK_FLOATS * (int)sizeof(float)
                   + WARPS * 2048 * (int)sizeof(u64);
    cudaFuncSetAttribute(pinn_kernel, cudaFuncAttributeMaxDynamicSharedMemorySize, smem);
    pinn_kernel<<<NPTS / PTS_PER_CTA, THREADS, smem>>>(x, y, t, Win, b_in, Wh, b_h,
                                                       Wout, b_out, out);
}